// round 14
// baseline (speedup 1.0000x reference)
#include <cuda_runtime.h>

#define NBINS 36
#define PS 32
#define WARPS_PER_BLOCK 8
#define THREADS (WARPS_PER_BLOCK * 32)
#define PATCHES_PER_BLOCK (WARPS_PER_BLOCK * 2)
#define CHUNK 4
#define NSPLIT 4

#define TWO_PI_F 6.283185307179586f
#define PI_F     3.14159265358979f

__global__ __launch_bounds__(THREADS, 6)
void orient_kernel(const float* __restrict__ x,
                   const float* __restrict__ gxw,
                   const float* __restrict__ gyw,
                   const float* __restrict__ smw,
                   const float* __restrict__ gk,
                   float* __restrict__ out,
                   int B)
{
    // four conflict-split sub-histograms per patch, selected by k&3
    __shared__ float shist[PATCHES_PER_BLOCK][NSPLIT][NBINS];
    __shared__ float sgk[PS * PS];

    for (int i = threadIdx.x; i < PS * PS; i += THREADS)
        sgk[i] = __ldg(gk + i);
    __syncthreads();

    const int warp = threadIdx.x >> 5;
    const int lane = threadIdx.x & 31;
    const int half = lane >> 4;          // which patch within the warp
    const int k    = lane & 15;          // column-pair index (cols 2k, 2k+1)
    const int hrow = warp * 2 + half;

    int patch = blockIdx.x * PATCHES_PER_BLOCK + hrow;
    const bool valid = (patch < B);
    if (!valid) patch = B - 1;           // clamp addressing; own hist row, no out write

    // zero all sub-hists: NSPLIT*36 = 144 floats per patch, 16 lanes -> 9 each
    float* hbase = &shist[hrow][0][0];
#pragma unroll
    for (int i = k; i < NSPLIT * NBINS; i += 16) hbase[i] = 0.0f;
    __syncwarp();

    float* hist = &shist[hrow][k & 3][0];   // this lane's sub-histogram

    const float wx0 = __ldg(gxw + 0), wx1 = __ldg(gxw + 1), wx2 = __ldg(gxw + 2);
    const float wy0 = __ldg(gyw + 0), wy1 = __ldg(gyw + 1), wy2 = __ldg(gyw + 2);
    const float rc = 1.0f / TWO_PI_F;    // RN(1/2pi), constant-folded

    const float2* p   = reinterpret_cast<const float2*>(x + (size_t)patch * (PS * PS)) + k;
    const float2* gk2 = reinterpret_cast<const float2*>(sgk) + k;

    // sliding window v[0..5] = rows c0-1 .. c0+4 (clamped); carry 2 rows across chunks
    float2 v[CHUNK + 2];
    {   // prologue for c0 = 0: rows -1(=0),0,1,2,3,4
        v[1] = __ldg(p + 0 * (PS / 2));
        v[0] = v[1];
        v[2] = __ldg(p + 1 * (PS / 2));
        v[3] = __ldg(p + 2 * (PS / 2));
        v[4] = __ldg(p + 3 * (PS / 2));
        v[5] = __ldg(p + 4 * (PS / 2));
    }

#pragma unroll 4
    for (int c0 = 0; c0 < PS; c0 += CHUNK) {
        if (c0 > 0) {
            // rotate carry: with unrolling this becomes pure register renaming
            v[0] = v[4];
            v[1] = v[5];
#pragma unroll
            for (int i = 0; i < CHUNK; ++i) {
                int r = c0 + 1 + i;                       // rows c0+1 .. c0+4
                r = (r > PS - 1) ? PS - 1 : r;
                v[2 + i] = __ldg(p + r * (PS / 2));
            }
        }

#pragma unroll
        for (int i = 0; i < CHUNK; ++i) {
            const int r = c0 + i;
            // gk row 0 is identically zero -> all pixels masked -> skip (bit-exact)
            if (r == 0) continue;

            const float2 b  = v[i + 1];
            const float2 up = v[i];
            const float2 dn = v[i + 2];

            float left_in  = __shfl_up_sync(0xffffffffu, b.y, 1);   // col 2k-1
            float right_in = __shfl_down_sync(0xffffffffu, b.x, 1); // col 2k+2
            if (k == 0)  left_in  = b.x;   // replicate pad (also kills cross-half leak)
            if (k == 15) right_in = b.y;

            const float2 g2 = gk2[r * (PS / 2)];

            // ---------------- pixel 0: column 2k ----------------
            {
                const float gx = wx0 * left_in + wx1 * b.x + wx2 * b.y;
                const float gy = wy0 * up.x    + wy1 * b.x + wy2 * dn.x;
                const float S = gx * gx + gy * gy + 1e-10f;
                float rs; asm("rsqrt.approx.f32 %0, %1;" : "=f"(rs) : "f"(S));
                const float mag = (S * rs) * g2.x;
                const float ori = atan2f(gy, gx);           // libdevice-exact, frozen
                const float m = (ori < 0.0f) ? (ori + TWO_PI_F) : ori;
                const float a36 = 36.0f * m;                // Markstein RN /2pi, frozen
                const float q0  = a36 * rc;
                const float rr  = fmaf(-TWO_PI_F, q0, a36);
                const float ob  = fmaf(rr, rc, q0);
                const float f = floorf(ob);
                const float wo1 = ob - f;
                int bin = (int)f;
                if (bin >= NBINS) bin -= NBINS;             // mod semantics (36 -> 0)
                const float w = fmaf(-wo1, mag, mag);       // (1-wo1)*mag, <=1ulp delta
                if (mag > 0.001f) atomicAdd(&hist[bin], w);
            }
            // ---------------- pixel 1: column 2k+1 ----------------
            {
                const float gx = wx0 * b.x + wx1 * b.y + wx2 * right_in;
                const float gy = wy0 * up.y + wy1 * b.y + wy2 * dn.y;
                const float S = gx * gx + gy * gy + 1e-10f;
                float rs; asm("rsqrt.approx.f32 %0, %1;" : "=f"(rs) : "f"(S));
                const float mag = (S * rs) * g2.y;
                const float ori = atan2f(gy, gx);
                const float m = (ori < 0.0f) ? (ori + TWO_PI_F) : ori;
                const float a36 = 36.0f * m;
                const float q0  = a36 * rc;
                const float rr  = fmaf(-TWO_PI_F, q0, a36);
                const float ob  = fmaf(rr, rc, q0);
                const float f = floorf(ob);
                const float wo1 = ob - f;
                int bin = (int)f;
                if (bin >= NBINS) bin -= NBINS;
                const float w = fmaf(-wo1, mag, mag);
                if (mag > 0.001f) atomicAdd(&hist[bin], w);
            }
        }
    }
    __syncwarp();

    // merge sub-histograms, then smoothing (conv3, zero pad) + argmax, per half-warp
    const float s0 = __ldg(smw + 0), s1 = __ldg(smw + 1), s2 = __ldg(smw + 2);
    const float inv = 1.0f / (float)(PS * PS);
    const float* h0 = &shist[hrow][0][0];
    const float* h1 = &shist[hrow][1][0];
    const float* h2 = &shist[hrow][2][0];
    const float* h3 = &shist[hrow][3][0];

#define HV(i) (((h0[(i)] + h1[(i)]) + (h2[(i)] + h3[(i)])) * inv)

    float bestv;
    int besti;
    {
        const int i = k;                              // bins 0..15
        const float hm = (i > 0) ? HV(i - 1) : 0.0f;
        const float hc = HV(i);
        const float hp = HV(i + 1);
        bestv = s0 * hm + s1 * hc + s2 * hp;
        besti = i;
    }
    {
        const int i = k + 16;                         // bins 16..31
        const float sm = s0 * HV(i - 1) + s1 * HV(i) + s2 * HV(i + 1);
        if (sm > bestv) { bestv = sm; besti = i; }    // strict >: lower index wins
    }
    if (k < 4) {                                      // bins 32..35
        const int i = k + 32;
        const float hp = (i + 1 < NBINS) ? HV(i + 1) : 0.0f;
        const float sm = s0 * HV(i - 1) + s1 * HV(i) + s2 * hp;
        if (sm > bestv) { bestv = sm; besti = i; }
    }
#undef HV
#pragma unroll
    for (int off = 8; off > 0; off >>= 1) {
        const float ov = __shfl_down_sync(0xffffffffu, bestv, off, 16);
        const int   oi = __shfl_down_sync(0xffffffffu, besti, off, 16);
        if (ov > bestv || (ov == bestv && oi < besti)) { bestv = ov; besti = oi; }
    }

    if (k == 0 && valid) {
        out[patch] = -((TWO_PI_F * (float)besti) / 36.0f - PI_F);
    }
}

extern "C" void kernel_launch(void* const* d_in, const int* in_sizes, int n_in,
                              void* d_out, int out_size)
{
    const float* x   = (const float*)d_in[0];
    const float* gxw = (const float*)d_in[1];
    const float* gyw = (const float*)d_in[2];
    const float* smw = (const float*)d_in[3];
    const float* gk  = (const float*)d_in[4];
    float* out = (float*)d_out;

    const int B = out_size;
    const int grid = (B + PATCHES_PER_BLOCK - 1) / PATCHES_PER_BLOCK;
    orient_kernel<<<grid, THREADS>>>(x, gxw, gyw, smw, gk, out, B);
}

// round 15
// speedup vs baseline: 1.0373x; 1.0373x over previous
#include <cuda_runtime.h>

#define NBINS 36
#define PS 32
#define WARPS_PER_BLOCK 8
#define THREADS (WARPS_PER_BLOCK * 32)
#define PATCHES_PER_BLOCK (WARPS_PER_BLOCK * 2)
#define CHUNK 4
#define NSPLIT 4

#define TWO_PI_F 6.283185307179586f
#define PI_F     3.14159265358979f

__global__ __launch_bounds__(THREADS, 6)
void orient_kernel(const float* __restrict__ x,
                   const float* __restrict__ gxw,
                   const float* __restrict__ gyw,
                   const float* __restrict__ smw,
                   const float* __restrict__ gk,
                   float* __restrict__ out,
                   int B)
{
    // four conflict-split sub-histograms per patch, selected by k&3
    __shared__ float shist[PATCHES_PER_BLOCK][NSPLIT][NBINS];
    __shared__ float sgk[PS * PS];

    for (int i = threadIdx.x; i < PS * PS; i += THREADS)
        sgk[i] = __ldg(gk + i);
    __syncthreads();

    const int warp = threadIdx.x >> 5;
    const int lane = threadIdx.x & 31;
    const int half = lane >> 4;          // which patch within the warp
    const int k    = lane & 15;          // column-pair index (cols 2k, 2k+1)
    const int hrow = warp * 2 + half;

    int patch = blockIdx.x * PATCHES_PER_BLOCK + hrow;
    const bool valid = (patch < B);
    if (!valid) patch = B - 1;           // clamp addressing; own hist row, no out write

    // zero all sub-hists: NSPLIT*36 = 144 floats per patch, 16 lanes -> 9 each
    float* hbase = &shist[hrow][0][0];
#pragma unroll
    for (int i = k; i < NSPLIT * NBINS; i += 16) hbase[i] = 0.0f;
    __syncwarp();

    float* hist = &shist[hrow][k & 3][0];   // this lane's sub-histogram

    const float wx0 = __ldg(gxw + 0), wx1 = __ldg(gxw + 1), wx2 = __ldg(gxw + 2);
    const float wy0 = __ldg(gyw + 0), wy1 = __ldg(gyw + 1), wy2 = __ldg(gyw + 2);
    const float rc = 1.0f / TWO_PI_F;    // RN(1/2pi), constant-folded

    const float2* p   = reinterpret_cast<const float2*>(x + (size_t)patch * (PS * PS)) + k;
    const float2* gk2 = reinterpret_cast<const float2*>(sgk) + k;

    // sliding window v[0..5] = rows c0-1 .. c0+4 (clamped); carry 2 rows across chunks
    float2 v[CHUNK + 2];
    {   // prologue for c0 = 0: rows -1(=0),0,1,2,3,4
        v[1] = __ldg(p + 0 * (PS / 2));
        v[0] = v[1];
        v[2] = __ldg(p + 1 * (PS / 2));
        v[3] = __ldg(p + 2 * (PS / 2));
        v[4] = __ldg(p + 3 * (PS / 2));
        v[5] = __ldg(p + 4 * (PS / 2));
    }

#pragma unroll 2
    for (int c0 = 0; c0 < PS; c0 += CHUNK) {
        if (c0 > 0) {
            // rotate carry: with unroll 2 the rotation between copies becomes renaming
            v[0] = v[4];
            v[1] = v[5];
#pragma unroll
            for (int i = 0; i < CHUNK; ++i) {
                int r = c0 + 1 + i;                       // rows c0+1 .. c0+4
                r = (r > PS - 1) ? PS - 1 : r;
                v[2 + i] = __ldg(p + r * (PS / 2));
            }
        }

#pragma unroll
        for (int i = 0; i < CHUNK; ++i) {
            const int r = c0 + i;
            // gk row 0 is identically zero -> all pixels masked -> skip (bit-exact)
            if (r == 0) continue;

            const float2 b  = v[i + 1];
            const float2 up = v[i];
            const float2 dn = v[i + 2];

            float left_in  = __shfl_up_sync(0xffffffffu, b.y, 1);   // col 2k-1
            float right_in = __shfl_down_sync(0xffffffffu, b.x, 1); // col 2k+2
            if (k == 0)  left_in  = b.x;   // replicate pad (also kills cross-half leak)
            if (k == 15) right_in = b.y;

            const float2 g2 = gk2[r * (PS / 2)];

            // ---------------- pixel 0: column 2k ----------------
            {
                const float gx = wx0 * left_in + wx1 * b.x + wx2 * b.y;
                const float gy = wy0 * up.x    + wy1 * b.x + wy2 * dn.x;
                const float S = gx * gx + gy * gy + 1e-10f;
                float rs; asm("rsqrt.approx.f32 %0, %1;" : "=f"(rs) : "f"(S));
                const float mag = (S * rs) * g2.x;
                const float ori = atan2f(gy, gx);           // libdevice-exact, frozen
                const float m = (ori < 0.0f) ? (ori + TWO_PI_F) : ori;
                const float a36 = 36.0f * m;                // Markstein RN /2pi, frozen
                const float q0  = a36 * rc;
                const float rr  = fmaf(-TWO_PI_F, q0, a36);
                const float ob  = fmaf(rr, rc, q0);
                const float f = floorf(ob);
                const float wo1 = ob - f;
                int bin = (int)f;
                if (bin >= NBINS) bin -= NBINS;             // mod semantics (36 -> 0)
                const float w = fmaf(-wo1, mag, mag);       // (1-wo1)*mag, <=1ulp delta
                if (mag > 0.001f) atomicAdd(&hist[bin], w);
            }
            // ---------------- pixel 1: column 2k+1 ----------------
            {
                const float gx = wx0 * b.x + wx1 * b.y + wx2 * right_in;
                const float gy = wy0 * up.y + wy1 * b.y + wy2 * dn.y;
                const float S = gx * gx + gy * gy + 1e-10f;
                float rs; asm("rsqrt.approx.f32 %0, %1;" : "=f"(rs) : "f"(S));
                const float mag = (S * rs) * g2.y;
                const float ori = atan2f(gy, gx);
                const float m = (ori < 0.0f) ? (ori + TWO_PI_F) : ori;
                const float a36 = 36.0f * m;
                const float q0  = a36 * rc;
                const float rr  = fmaf(-TWO_PI_F, q0, a36);
                const float ob  = fmaf(rr, rc, q0);
                const float f = floorf(ob);
                const float wo1 = ob - f;
                int bin = (int)f;
                if (bin >= NBINS) bin -= NBINS;
                const float w = fmaf(-wo1, mag, mag);
                if (mag > 0.001f) atomicAdd(&hist[bin], w);
            }
        }
    }
    __syncwarp();

    // merge sub-histograms, then smoothing (conv3, zero pad) + argmax, per half-warp
    const float s0 = __ldg(smw + 0), s1 = __ldg(smw + 1), s2 = __ldg(smw + 2);
    const float inv = 1.0f / (float)(PS * PS);
    const float* h0 = &shist[hrow][0][0];
    const float* h1 = &shist[hrow][1][0];
    const float* h2 = &shist[hrow][2][0];
    const float* h3 = &shist[hrow][3][0];

#define HV(i) (((h0[(i)] + h1[(i)]) + (h2[(i)] + h3[(i)])) * inv)

    float bestv;
    int besti;
    {
        const int i = k;                              // bins 0..15
        const float hm = (i > 0) ? HV(i - 1) : 0.0f;
        const float hc = HV(i);
        const float hp = HV(i + 1);
        bestv = s0 * hm + s1 * hc + s2 * hp;
        besti = i;
    }
    {
        const int i = k + 16;                         // bins 16..31
        const float sm = s0 * HV(i - 1) + s1 * HV(i) + s2 * HV(i + 1);
        if (sm > bestv) { bestv = sm; besti = i; }    // strict >: lower index wins
    }
    if (k < 4) {                                      // bins 32..35
        const int i = k + 32;
        const float hp = (i + 1 < NBINS) ? HV(i + 1) : 0.0f;
        const float sm = s0 * HV(i - 1) + s1 * HV(i) + s2 * hp;
        if (sm > bestv) { bestv = sm; besti = i; }
    }
#undef HV
#pragma unroll
    for (int off = 8; off > 0; off >>= 1) {
        const float ov = __shfl_down_sync(0xffffffffu, bestv, off, 16);
        const int   oi = __shfl_down_sync(0xffffffffu, besti, off, 16);
        if (ov > bestv || (ov == bestv && oi < besti)) { bestv = ov; besti = oi; }
    }

    if (k == 0 && valid) {
        out[patch] = -((TWO_PI_F * (float)besti) / 36.0f - PI_F);
    }
}

extern "C" void kernel_launch(void* const* d_in, const int* in_sizes, int n_in,
                              void* d_out, int out_size)
{
    const float* x   = (const float*)d_in[0];
    const float* gxw = (const float*)d_in[1];
    const float* gyw = (const float*)d_in[2];
    const float* smw = (const float*)d_in[3];
    const float* gk  = (const float*)d_in[4];
    float* out = (float*)d_out;

    const int B = out_size;
    const int grid = (B + PATCHES_PER_BLOCK - 1) / PATCHES_PER_BLOCK;
    orient_kernel<<<grid, THREADS>>>(x, gxw, gyw, smw, gk, out, B);
}